// round 3
// baseline (speedup 1.0000x reference)
#include <cuda_runtime.h>

// Problem constants (fixed by setup_inputs)
namespace {
constexpr int B = 8, C = 64, H = 256, W = 512, SW = 128;
constexpr int HW = H * W;               // 131072 = 2^17
constexpr int NPTS = B * HW;            // 1048576
constexpr int CELLS_PER_B = SW * SW;    // 16384
constexpr int NCELL = B * CELLS_PER_B;  // 131072
constexpr int NOUT = B * C * CELLS_PER_B; // 8388608
}

// Scratch (static __device__ arrays — no allocation)
__device__ float g_sphi[H], g_cphi[H], g_sth[W], g_cth[W];
__device__ unsigned int g_maxh_bits;            // orderable-uint of global max valid y
__device__ unsigned long long g_best[NCELL];    // (ord(h)<<32)|idx_in_batch, 0 = empty
__device__ int   g_cell[NPTS];                  // cell id or -1
__device__ float g_yval[NPTS];                  // y per point

// Monotonic float<->uint mapping (preserves full IEEE ordering)
__device__ __forceinline__ unsigned int ford(float f) {
    unsigned int b = __float_as_uint(f);
    return (b & 0x80000000u) ? ~b : (b | 0x80000000u);
}
__device__ __forceinline__ float fdeord(unsigned int u) {
    unsigned int b = (u & 0x80000000u) ? (u & 0x7FFFFFFFu) : ~u;
    return __uint_as_float(b);
}

__global__ void k_init() {
    int t = blockIdx.x * blockDim.x + threadIdx.x;
    if (t < NCELL) g_best[t] = 0ull;
    if (t == 0) g_maxh_bits = 0u;   // below ord() of any finite float
}

// Mirror jnp.linspace(0, 2pi, W) / (0, pi, H) in f32:
//   delta = f32(stop)/f32(num-1); out[k] = k*delta; out[num-1] = stop (endpoint)
__global__ void k_tables() {
    int t = threadIdx.x;
    const float TWO_PI = 6.28318530717958647692f;  // rounds to f32(2*pi)
    const float PI_F   = 3.14159265358979323846f;  // rounds to f32(pi)
    if (t < W) {
        float dth = __fdiv_rn(TWO_PI, 511.0f);
        float th  = (t == W - 1) ? TWO_PI : __fmul_rn((float)t, dth);
        g_sth[t] = sinf(th);
        g_cth[t] = cosf(th);
    }
    if (t < H) {
        float dph = __fdiv_rn(PI_F, 255.0f);
        float ph  = (t == H - 1) ? PI_F : __fmul_rn((float)t, dph);
        g_sphi[t] = sinf(ph);
        g_cphi[t] = cosf(ph);
    }
}

// Pass 1: per-point projection, cache (cell, y), global max of valid y.
__global__ void k_point(const float* __restrict__ depth,
                        const float* __restrict__ mpp) {
    int p = blockIdx.x * blockDim.x + threadIdx.x;  // grid sized exactly NPTS
    int j = p & (W - 1);
    int i = (p >> 9) & (H - 1);
    int b = p >> 17;

    float sph = g_sphi[i], cph = g_cphi[i];
    float sth = g_sth[j],  cth = g_cth[j];
    float d = depth[p];
    float m = __ldg(&mpp[b]);

    // Rotated coords, exact f32 op order of the eager XLA graph:
    //   X = ((-sinphi)*sintheta)*d ; Y = (-cosphi)*d ; Z = (-(sinphi*costheta))*d
    float X = __fmul_rn(__fmul_rn(-sph, sth), d);
    float Y = __fmul_rn(-cph, d);
    float Z = __fmul_rn(-__fmul_rn(sph, cth), d);

    float x = truncf(__fdiv_rn(X, m));
    float z = truncf(__fdiv_rn(Z, m));
    bool valid = (x >= -64.0f) && (x <= 63.0f) && (z >= -64.0f) && (z <= 63.0f);

    int cell = -1;
    unsigned v = 0u;
    if (valid) {
        cell = b * CELLS_PER_B + ((int)x + 64) * SW + ((int)z + 64);
        v = ford(Y);
    }
    g_cell[p] = cell;
    g_yval[p] = Y;

    // block-reduce max(ord(y)) -> one atomic per block
    v = __reduce_max_sync(0xFFFFFFFFu, v);
    __shared__ unsigned sm[8];
    int lane = threadIdx.x & 31, wid = threadIdx.x >> 5;
    if (lane == 0) sm[wid] = v;
    __syncthreads();
    if (wid == 0) {
        unsigned t = (lane < (int)(blockDim.x >> 5)) ? sm[lane] : 0u;
        t = __reduce_max_sync(0xFFFFFFFFu, t);
        if (lane == 0 && t) atomicMax(&g_maxh_bits, t);
    }
}

// Pass 2: key = (ord(max_h - y) << 32) | idx_in_batch; atomicMax per cell.
// Reproduces lexsort((h, cell)) + keep-last: max h, ties -> max original index.
__global__ void k_key() {
    int p = blockIdx.x * blockDim.x + threadIdx.x;
    int cell = g_cell[p];
    if (cell < 0) return;
    float maxh = fdeord(g_maxh_bits);
    float h = __fsub_rn(maxh, g_yval[p]);
    unsigned long long key =
        ((unsigned long long)ford(h) << 32) | (unsigned)(p & (HW - 1));
    atomicMax(&g_best[cell], key);
}

// Pass 3: gather winner pixels into [B, C, SW, SW]; empty cell -> 0.
// t maps z fastest -> coalesced writes; best[] reads coalesced & L2-resident.
__global__ void k_gather(const float* __restrict__ img,
                         float* __restrict__ out) {
    int t = blockIdx.x * blockDim.x + threadIdx.x;
    if (t >= NOUT) return;
    int z = t & (SW - 1);
    int x = (t >> 7) & (SW - 1);
    int c = (t >> 14) & (C - 1);
    int b = t >> 20;
    unsigned long long best = g_best[b * CELLS_PER_B + x * SW + z];
    float val = 0.0f;
    if (best) {
        int r = (int)(best & 0xFFFFFFFFull);  // i*W + j within batch
        val = __ldg(&img[(b * C + c) * HW + r]);
    }
    out[t] = val;
}

extern "C" void kernel_launch(void* const* d_in, const int* in_sizes, int n_in,
                              void* d_out, int out_size) {
    const float* img   = (const float*)d_in[0];  // [B,C,H,W]
    const float* depth = (const float*)d_in[1];  // [B,1,H,W]
    const float* mpp   = (const float*)d_in[2];  // [B]
    float* out = (float*)d_out;                  // [B,C,SW,SW]

    k_init<<<(NCELL + 255) / 256, 256>>>();
    k_tables<<<1, 512>>>();
    k_point<<<NPTS / 256, 256>>>(depth, mpp);
    k_key<<<NPTS / 256, 256>>>();
    k_gather<<<(NOUT + 255) / 256, 256>>>(img, out);
}

// round 5
// speedup vs baseline: 1.0987x; 1.0987x over previous
#include <cuda_runtime.h>

// Problem constants (fixed by setup_inputs)
namespace {
constexpr int B = 8, C = 64, H = 256, W = 512, SW = 128;
constexpr int HW = H * W;                 // 131072 = 2^17
constexpr int NPTS = B * HW;              // 1048576
constexpr int CPB = SW * SW;              // 16384
constexpr int NCELL = B * CPB;            // 131072
constexpr int NOUT = B * C * CPB;         // 8388608
}

// Scratch (static __device__ arrays — no allocation)
__device__ float g_sphi[H], g_cphi[H], g_sth[W], g_cth[W];
__device__ unsigned int g_maxh_bits;              // orderable-uint of global max valid y
__device__ unsigned long long g_best[NCELL];      // (ord(h)<<32)|idx_in_batch, 0 = empty

// Monotonic float<->uint mapping (preserves full IEEE ordering)
__device__ __forceinline__ unsigned int ford(float f) {
    unsigned int b = __float_as_uint(f);
    return (b & 0x80000000u) ? ~b : (b | 0x80000000u);
}
__device__ __forceinline__ float fdeord(unsigned int u) {
    unsigned int b = (u & 0x80000000u) ? (u & 0x7FFFFFFFu) : ~u;
    return __uint_as_float(b);
}

__global__ void k_init() {
    int t = blockIdx.x * blockDim.x + threadIdx.x;   // NCELL/2 threads
    reinterpret_cast<ulonglong2*>(g_best)[t] = make_ulonglong2(0ull, 0ull);
    if (t == 0) g_maxh_bits = 0u;
}

// Mirror jnp.linspace(0, 2pi, W) / (0, pi, H) in f32:
//   delta = f32(stop)/f32(num-1); out[k] = k*delta; out[num-1] = stop
__global__ void k_tables() {
    int t = threadIdx.x;
    const float TWO_PI = 6.28318530717958647692f;
    const float PI_F   = 3.14159265358979323846f;
    if (t < W) {
        float dth = __fdiv_rn(TWO_PI, 511.0f);
        float th  = (t == W - 1) ? TWO_PI : __fmul_rn((float)t, dth);
        g_sth[t] = sinf(th);
        g_cth[t] = cosf(th);
    }
    if (t < H) {
        float dph = __fdiv_rn(PI_F, 255.0f);
        float ph  = (t == H - 1) ? PI_F : __fmul_rn((float)t, dph);
        g_sphi[t] = sinf(ph);
        g_cphi[t] = cosf(ph);
    }
}

// Exact f32 op order of the eager XLA graph:
//   X = ((-sinphi)*sintheta)*d ; Y = (-cosphi)*d ; Z = (-(sinphi*costheta))*d
// Returns cell id (or -1 if invalid) and y.
__device__ __forceinline__ int project(int p, float d, float m, float& y) {
    int j = p & (W - 1);
    int i = (p >> 9) & (H - 1);
    int b = p >> 17;
    float sph = __ldg(&g_sphi[i]), cph = __ldg(&g_cphi[i]);
    float sth = __ldg(&g_sth[j]),  cth = __ldg(&g_cth[j]);
    float X = __fmul_rn(__fmul_rn(-sph, sth), d);
    y       = __fmul_rn(-cph, d);
    float Z = __fmul_rn(-__fmul_rn(sph, cth), d);
    float x = truncf(__fdiv_rn(X, m));
    float z = truncf(__fdiv_rn(Z, m));
    bool valid = (x >= -64.0f) && (x <= 63.0f) && (z >= -64.0f) && (z <= 63.0f);
    return valid ? b * CPB + ((int)x + 64) * SW + ((int)z + 64) : -1;
}

// Pass 1: global max of valid y. Pure reduction, 4 points per thread (float4).
__global__ void k_maxy(const float* __restrict__ depth,
                       const float* __restrict__ mpp) {
    int t = blockIdx.x * blockDim.x + threadIdx.x;  // NPTS/4 threads
    int p0 = t * 4;
    float4 d4 = *reinterpret_cast<const float4*>(&depth[p0]);
    float m = __ldg(&mpp[p0 >> 17]);
    unsigned v = 0u;
    float y;
    if (project(p0 + 0, d4.x, m, y) >= 0) v = max(v, ford(y));
    if (project(p0 + 1, d4.y, m, y) >= 0) v = max(v, ford(y));
    if (project(p0 + 2, d4.z, m, y) >= 0) v = max(v, ford(y));
    if (project(p0 + 3, d4.w, m, y) >= 0) v = max(v, ford(y));

    v = __reduce_max_sync(0xFFFFFFFFu, v);
    __shared__ unsigned sm[8];
    int lane = threadIdx.x & 31, wid = threadIdx.x >> 5;
    if (lane == 0) sm[wid] = v;
    __syncthreads();
    if (wid == 0) {
        unsigned u = (lane < (int)(blockDim.x >> 5)) ? sm[lane] : 0u;
        u = __reduce_max_sync(0xFFFFFFFFu, u);
        if (lane == 0 && u) atomicMax(&g_maxh_bits, u);
    }
}

// Pass 2: key = (ord(max_h - y) << 32) | idx; warp-aggregated atomicMax per cell.
// Reproduces lexsort((h, cell)) + keep-last: max h, ties -> max original index.
__global__ void k_key(const float* __restrict__ depth,
                      const float* __restrict__ mpp) {
    int p = blockIdx.x * blockDim.x + threadIdx.x;
    float d = depth[p];
    float m = __ldg(&mpp[p >> 17]);
    float y;
    int cell = project(p, d, m, y);

    float maxh = fdeord(g_maxh_bits);
    unsigned long long key = 0ull;
    if (cell >= 0) {
        float h = __fsub_rn(maxh, y);
        key = ((unsigned long long)ford(h) << 32) | (unsigned)(p & (HW - 1));
    }

    // Segmented suffix-max over same-cell lane runs (adjacent theta -> long
    // runs exactly on the contended center cells). Leader of each run does
    // one atomic carrying the run max. Cross-run same-cell merges are
    // harmless for max semantics.
    int lane = threadIdx.x & 31;
    #pragma unroll
    for (int dl = 1; dl < 32; dl <<= 1) {
        unsigned long long ok = __shfl_down_sync(0xFFFFFFFFu, key, dl);
        int oc = __shfl_down_sync(0xFFFFFFFFu, cell, dl);
        if (lane + dl < 32 && oc == cell && ok > key) key = ok;
    }
    int pc = __shfl_up_sync(0xFFFFFFFFu, cell, 1);
    bool leader = (lane == 0) || (pc != cell);

    if (leader && cell >= 0) {
        // Monotonic pre-read filter: any cached/stale value is a valid lower
        // bound, so skipping when cur >= key is always safe.
        unsigned long long cur = g_best[cell];
        if (key > cur) atomicMax(&g_best[cell], key);
    }
}

// Pass 3: gather winner pixels into [B, C, SW, SW]; empty cell -> 0.
// 4 z-adjacent cells per thread: one 32B best read, 4 independent scattered
// image loads (MLP=4), one coalesced float4 store.
__global__ void k_gather(const float* __restrict__ img,
                         float* __restrict__ out) {
    int t = blockIdx.x * blockDim.x + threadIdx.x;  // NOUT/4 threads
    int z4 = t & 31;
    int x  = (t >> 5) & (SW - 1);
    int c  = (t >> 12) & (C - 1);
    int b  = t >> 18;

    const unsigned long long* bp = &g_best[b * CPB + x * SW + z4 * 4];
    ulonglong2 b01 = *reinterpret_cast<const ulonglong2*>(bp);
    ulonglong2 b23 = *reinterpret_cast<const ulonglong2*>(bp + 2);

    const float* ip = &img[(b * C + c) * HW];
    float4 v = make_float4(0.f, 0.f, 0.f, 0.f);
    if (b01.x) v.x = __ldg(&ip[(unsigned)(b01.x & 0xFFFFFFFFull)]);
    if (b01.y) v.y = __ldg(&ip[(unsigned)(b01.y & 0xFFFFFFFFull)]);
    if (b23.x) v.z = __ldg(&ip[(unsigned)(b23.x & 0xFFFFFFFFull)]);
    if (b23.y) v.w = __ldg(&ip[(unsigned)(b23.y & 0xFFFFFFFFull)]);

    *reinterpret_cast<float4*>(&out[t * 4]) = v;
}

extern "C" void kernel_launch(void* const* d_in, const int* in_sizes, int n_in,
                              void* d_out, int out_size) {
    const float* img   = (const float*)d_in[0];  // [B,C,H,W]
    const float* depth = (const float*)d_in[1];  // [B,1,H,W]
    const float* mpp   = (const float*)d_in[2];  // [B]
    float* out = (float*)d_out;                  // [B,C,SW,SW]

    k_init<<<(NCELL / 2) / 256, 256>>>();
    k_tables<<<1, 512>>>();
    k_maxy<<<(NPTS / 4) / 256, 256>>>(depth, mpp);
    k_key<<<NPTS / 256, 256>>>(depth, mpp);
    k_gather<<<(NOUT / 4) / 256, 256>>>(img, out);
}